// round 8
// baseline (speedup 1.0000x reference)
#include <cuda_runtime.h>
#include <math.h>

// ---------------------------------------------------------------------------
// TrLaplacianDP: out = embs + noise, where noise[0:300] are the first 300
// accepted samples of a truncated-Laplacian rejection scan over (sgn, u).
//
// R8: R7 + EXPLICIT PDL trigger. The noise kernel fires
// cudaTriggerProgrammaticLaunchCompletion() right after its g_noise writes,
// so the add grid launches (and runs its pre-sync embs prefetch) while the
// noise kernel is still tearing down, instead of waiting for its implicit
// end-of-kernel trigger.
// ---------------------------------------------------------------------------

#define EMBS_DIM 300
#define T_N      1024
#define NCHUNK   (T_N * 4)            // 4096 samples per scan chunk

#define ADD_GRID  4800
#define ADD_BLK   256
#define ADD_IT    8
#define ADD_STRIDE (ADD_GRID * ADD_BLK)   // 1228800 = 75 * 16384

__device__ __align__(16) float g_noise[304];   // 75 float4 + pad

__device__ __forceinline__ float sign_of(float x) {
    return (x > 0.0f) ? 1.0f : ((x < 0.0f) ? -1.0f : 0.0f);
}

// ---------------------------------------------------------------------------
// Kernel N: single-block ordered rejection scan, log-free mask.
// |r| <= A  <=>  u >= 1 - 2/sqrt(300); logf only for stored values (~300).
// Boundary band (|u-thr|<2e-5 or sgn==0) uses the exact log path.
// Expected accepts in chunk 0: 4096 * 0.1155 = 473 >= 300 -> one chunk.
// ---------------------------------------------------------------------------
__global__ void __launch_bounds__(T_N) noise_kernel(const float* __restrict__ sgn,
                                                    const float* __restrict__ u,
                                                    int n) {
    const double SCALE_D = 2.0 * 0.005 * sqrt(300.0) / 1.0;
    const float  SCALE_F = (float)SCALE_D;
    const float  A_F     = (float)(-SCALE_D * log(1.0 - 2.0 * 1.0 / sqrt(300.0)));
    const float  U_THR   = (float)(1.0 - 2.0 / sqrt(300.0));   // exp(-A/SCALE)
    const float  BAND    = 2e-5f;

    __shared__ int s_wsum[32];
    __shared__ int s_carry, s_total;

    const int tid  = threadIdx.x;
    const int lane = tid & 31;
    const int wid  = tid >> 5;

    if (tid < 304) g_noise[tid] = 0.0f;
    if (tid == 0) s_carry = 0;
    __syncthreads();

    for (int base = 0; base < n; base += NCHUNK) {
        const int i0 = base + tid * 4;
        float sv[4], uv[4];
        bool  have[4], m[4], rdone[4];
        float rv[4];

        if (i0 + 3 < n) {
            const float4 s4 = *reinterpret_cast<const float4*>(sgn + i0);
            const float4 u4 = *reinterpret_cast<const float4*>(u + i0);
            sv[0]=s4.x; sv[1]=s4.y; sv[2]=s4.z; sv[3]=s4.w;
            uv[0]=u4.x; uv[1]=u4.y; uv[2]=u4.z; uv[3]=u4.w;
            have[0]=have[1]=have[2]=have[3]=true;
        } else {
            #pragma unroll
            for (int j = 0; j < 4; ++j) {
                const int i = i0 + j;
                have[j] = (i < n);
                sv[j] = have[j] ? sgn[i] : 0.0f;
                uv[j] = have[j] ? u[i]   : 0.0f;   // u=0 -> fast reject
            }
        }

        int cnt = 0;
        #pragma unroll
        for (int j = 0; j < 4; ++j) {
            rdone[j] = false; rv[j] = 0.0f;
            if (fabsf(uv[j] - U_THR) < BAND || sv[j] == 0.0f) {
                const float s = sign_of(sv[j]);
                float r = (-SCALE_F * s) * logf(uv[j]);
                if (fabsf(fabsf(r) - A_F) < 1e-4f)
                    r = (-SCALE_F * s) * (float)log((double)uv[j]);
                m[j] = have[j] && (r >= -A_F) && (r <= A_F);
                rv[j] = r; rdone[j] = true;
            } else {
                m[j] = have[j] && (uv[j] >= U_THR);   // log-free mask
            }
            cnt += m[j] ? 1 : 0;
        }

        int incl = cnt;
        #pragma unroll
        for (int o = 1; o < 32; o <<= 1) {
            const int v = __shfl_up_sync(0xffffffffu, incl, o);
            if (lane >= o) incl += v;
        }
        if (lane == 31) s_wsum[wid] = incl;
        __syncthreads();

        if (wid == 0) {
            const int v = s_wsum[lane];
            int iv = v;
            #pragma unroll
            for (int o = 1; o < 32; o <<= 1) {
                const int x = __shfl_up_sync(0xffffffffu, iv, o);
                if (lane >= o) iv += x;
            }
            s_wsum[lane] = iv - v;
            if (lane == 31) s_total = iv;
        }
        __syncthreads();

        int pos = s_carry + s_wsum[wid] + (incl - cnt);
        #pragma unroll
        for (int j = 0; j < 4; ++j) {
            if (m[j]) {
                if (pos < EMBS_DIM) {
                    float r = rv[j];
                    if (!rdone[j])
                        r = (-SCALE_F * sign_of(sv[j])) * logf(uv[j]);
                    g_noise[pos] = r;
                }
                ++pos;
            }
        }
        __syncthreads();
        if (tid == 0) s_carry += s_total;
        __syncthreads();
        if (s_carry >= EMBS_DIM) break;          // uniform
    }

    // All g_noise writes are done (per-thread program order + the barriers
    // above). Fire the PDL trigger now so the dependent add grid launches
    // before this kernel finishes draining/exiting.
    __threadfence();
    cudaTriggerProgrammaticLaunchCompletion();
}

// ---------------------------------------------------------------------------
// Kernel B (exact fit): prefetch embs BEFORE the PDL grid sync, then add.
// ---------------------------------------------------------------------------
__global__ void __launch_bounds__(ADD_BLK) add_exact_kernel(
        const float* __restrict__ embs, float* __restrict__ out) {
    const float4* __restrict__ in4  = reinterpret_cast<const float4*>(embs);
    float4* __restrict__       out4 = reinterpret_cast<float4*>(out);

    const int v0 = blockIdx.x * ADD_BLK + threadIdx.x;

    // ---- Pre-sync: everything independent of g_noise. ----
    const float4* nzp = &reinterpret_cast<const float4*>(g_noise)[v0 % 75];
    float4 e[ADD_IT];
    #pragma unroll
    for (int k = 0; k < ADD_IT; ++k)
        e[k] = __ldcs(&in4[v0 + k * ADD_STRIDE]);

    // ---- Wait for noise kernel's g_noise writes (no-op without PDL). ----
    cudaGridDependencySynchronize();

    const float4 nz = *nzp;   // L2-broadcast LDG.128; loop-invariant

    #pragma unroll
    for (int k = 0; k < ADD_IT; ++k) {
        float4 t = e[k];
        t.x += nz.x; t.y += nz.y; t.z += nz.z; t.w += nz.w;
        __stcs(&out4[v0 + k * ADD_STRIDE], t);
    }
}

// ---------------------------------------------------------------------------
// Kernel B (general fallback): any shape. PDL-aware.
// ---------------------------------------------------------------------------
__global__ void __launch_bounds__(256) add_general_kernel(
        const float* __restrict__ embs, float* __restrict__ out,
        int n4, int n) {
    cudaGridDependencySynchronize();

    const float4* __restrict__ in4  = reinterpret_cast<const float4*>(embs);
    float4* __restrict__       out4 = reinterpret_cast<float4*>(out);

    const int stride = gridDim.x * blockDim.x;       // multiple of 75
    const int v0     = blockIdx.x * blockDim.x + threadIdx.x;
    const float4 nz  = reinterpret_cast<const float4*>(g_noise)[v0 % 75];

    for (int v = v0; v < n4; v += 8 * stride) {
        #pragma unroll
        for (int k = 0; k < 8; ++k) {
            const int vi = v + k * stride;
            if (vi < n4) {
                float4 t = __ldcs(&in4[vi]);
                t.x += nz.x; t.y += nz.y; t.z += nz.z; t.w += nz.w;
                __stcs(&out4[vi], t);
            }
        }
    }
    const int tail_start = n4 * 4;
    for (int i = tail_start + v0; i < n; i += stride)
        out[i] = embs[i] + g_noise[i % EMBS_DIM];
}

// ---------------------------------------------------------------------------
extern "C" void kernel_launch(void* const* d_in, const int* in_sizes, int n_in,
                              void* d_out, int out_size) {
    const float* embs = (const float*)d_in[0];
    const float* sgn  = (const float*)d_in[1];
    const float* u    = (const float*)d_in[2];
    float* out        = (float*)d_out;

    const int nsamp = in_sizes[1];
    noise_kernel<<<1, T_N>>>(sgn, u, nsamp);

    const int n  = out_size;
    const int n4 = n / 4;

    if (n == n4 * 4 && n4 == ADD_GRID * ADD_BLK * ADD_IT) {
        cudaLaunchConfig_t cfg = {};
        cfg.gridDim  = dim3(ADD_GRID, 1, 1);
        cfg.blockDim = dim3(ADD_BLK, 1, 1);
        cudaLaunchAttribute attr[1];
        attr[0].id = cudaLaunchAttributeProgrammaticStreamSerialization;
        attr[0].val.programmaticStreamSerializationAllowed = 1;
        cfg.attrs = attr;
        cfg.numAttrs = 1;
        cudaError_t e = cudaLaunchKernelEx(&cfg, add_exact_kernel, embs, out);
        if (e != cudaSuccess) {
            (void)cudaGetLastError();               // clear sticky error
            add_exact_kernel<<<ADD_GRID, ADD_BLK>>>(embs, out);
        }
    } else {
        int grid = (n4 + 256 * 8 - 1) / (256 * 8);
        grid = ((grid + 74) / 75) * 75;             // stride % 75 == 0
        if (grid < 75) grid = 75;
        add_general_kernel<<<grid, 256>>>(embs, out, n4, n);
    }
}

// round 9
// speedup vs baseline: 1.0666x; 1.0666x over previous
#include <cuda_runtime.h>
#include <math.h>

// ---------------------------------------------------------------------------
// TrLaplacianDP: out = embs + noise, where noise[0:300] are the first 300
// accepted samples of a truncated-Laplacian rejection scan over (sgn, u).
//
// R9: PDL trigger moved to the FIRST instruction of the noise kernel.
// The trigger only gates when the dependent grid LAUNCHES; the add kernel's
// cudaGridDependencySynchronize() still waits for noise-kernel completion,
// so correctness is unchanged — but now the add grid's pre-sync embs
// prefetch (8 cold LDG.128/thread across 147 otherwise-idle SMs) runs
// concurrently with the entire 1-SM noise scan, taking it off the
// critical path.
// ---------------------------------------------------------------------------

#define EMBS_DIM 300
#define T_N      1024
#define NCHUNK   (T_N * 4)            // 4096 samples per scan chunk

#define ADD_GRID  4800
#define ADD_BLK   256
#define ADD_IT    8
#define ADD_STRIDE (ADD_GRID * ADD_BLK)   // 1228800 = 75 * 16384

__device__ __align__(16) float g_noise[304];   // 75 float4 + pad

__device__ __forceinline__ float sign_of(float x) {
    return (x > 0.0f) ? 1.0f : ((x < 0.0f) ? -1.0f : 0.0f);
}

// ---------------------------------------------------------------------------
// Kernel N: single-block ordered rejection scan, log-free mask.
// |r| <= A  <=>  u >= 1 - 2/sqrt(300); logf only for stored values (~300).
// Boundary band (|u-thr|<2e-5 or sgn==0) uses the exact log path.
// ---------------------------------------------------------------------------
__global__ void __launch_bounds__(T_N) noise_kernel(const float* __restrict__ sgn,
                                                    const float* __restrict__ u,
                                                    int n) {
    // Release the dependent add grid IMMEDIATELY. Ordering of g_noise is
    // enforced by the secondary's cudaGridDependencySynchronize(), which
    // waits for this grid's completion — the trigger only unlocks launch.
    cudaTriggerProgrammaticLaunchCompletion();

    const double SCALE_D = 2.0 * 0.005 * sqrt(300.0) / 1.0;
    const float  SCALE_F = (float)SCALE_D;
    const float  A_F     = (float)(-SCALE_D * log(1.0 - 2.0 * 1.0 / sqrt(300.0)));
    const float  U_THR   = (float)(1.0 - 2.0 / sqrt(300.0));   // exp(-A/SCALE)
    const float  BAND    = 2e-5f;

    __shared__ int s_wsum[32];
    __shared__ int s_carry, s_total;

    const int tid  = threadIdx.x;
    const int lane = tid & 31;
    const int wid  = tid >> 5;

    if (tid < 304) g_noise[tid] = 0.0f;
    if (tid == 0) s_carry = 0;
    __syncthreads();

    for (int base = 0; base < n; base += NCHUNK) {
        const int i0 = base + tid * 4;
        float sv[4], uv[4];
        bool  have[4], m[4], rdone[4];
        float rv[4];

        if (i0 + 3 < n) {
            const float4 s4 = *reinterpret_cast<const float4*>(sgn + i0);
            const float4 u4 = *reinterpret_cast<const float4*>(u + i0);
            sv[0]=s4.x; sv[1]=s4.y; sv[2]=s4.z; sv[3]=s4.w;
            uv[0]=u4.x; uv[1]=u4.y; uv[2]=u4.z; uv[3]=u4.w;
            have[0]=have[1]=have[2]=have[3]=true;
        } else {
            #pragma unroll
            for (int j = 0; j < 4; ++j) {
                const int i = i0 + j;
                have[j] = (i < n);
                sv[j] = have[j] ? sgn[i] : 0.0f;
                uv[j] = have[j] ? u[i]   : 0.0f;   // u=0 -> fast reject
            }
        }

        int cnt = 0;
        #pragma unroll
        for (int j = 0; j < 4; ++j) {
            rdone[j] = false; rv[j] = 0.0f;
            if (fabsf(uv[j] - U_THR) < BAND || sv[j] == 0.0f) {
                const float s = sign_of(sv[j]);
                float r = (-SCALE_F * s) * logf(uv[j]);
                if (fabsf(fabsf(r) - A_F) < 1e-4f)
                    r = (-SCALE_F * s) * (float)log((double)uv[j]);
                m[j] = have[j] && (r >= -A_F) && (r <= A_F);
                rv[j] = r; rdone[j] = true;
            } else {
                m[j] = have[j] && (uv[j] >= U_THR);   // log-free mask
            }
            cnt += m[j] ? 1 : 0;
        }

        int incl = cnt;
        #pragma unroll
        for (int o = 1; o < 32; o <<= 1) {
            const int v = __shfl_up_sync(0xffffffffu, incl, o);
            if (lane >= o) incl += v;
        }
        if (lane == 31) s_wsum[wid] = incl;
        __syncthreads();

        if (wid == 0) {
            const int v = s_wsum[lane];
            int iv = v;
            #pragma unroll
            for (int o = 1; o < 32; o <<= 1) {
                const int x = __shfl_up_sync(0xffffffffu, iv, o);
                if (lane >= o) iv += x;
            }
            s_wsum[lane] = iv - v;
            if (lane == 31) s_total = iv;
        }
        __syncthreads();

        int pos = s_carry + s_wsum[wid] + (incl - cnt);
        #pragma unroll
        for (int j = 0; j < 4; ++j) {
            if (m[j]) {
                if (pos < EMBS_DIM) {
                    float r = rv[j];
                    if (!rdone[j])
                        r = (-SCALE_F * sign_of(sv[j])) * logf(uv[j]);
                    g_noise[pos] = r;
                }
                ++pos;
            }
        }
        __syncthreads();
        if (tid == 0) s_carry += s_total;
        __syncthreads();
        if (s_carry >= EMBS_DIM) break;          // uniform
    }
}

// ---------------------------------------------------------------------------
// Kernel B (exact fit): prefetch embs BEFORE the PDL grid sync, then add.
// ---------------------------------------------------------------------------
__global__ void __launch_bounds__(ADD_BLK) add_exact_kernel(
        const float* __restrict__ embs, float* __restrict__ out) {
    const float4* __restrict__ in4  = reinterpret_cast<const float4*>(embs);
    float4* __restrict__       out4 = reinterpret_cast<float4*>(out);

    const int v0 = blockIdx.x * ADD_BLK + threadIdx.x;

    // ---- Pre-sync: everything independent of g_noise. ----
    const float4* nzp = &reinterpret_cast<const float4*>(g_noise)[v0 % 75];
    float4 e[ADD_IT];
    #pragma unroll
    for (int k = 0; k < ADD_IT; ++k)
        e[k] = __ldcs(&in4[v0 + k * ADD_STRIDE]);

    // ---- Wait for noise kernel completion (no-op without PDL). ----
    cudaGridDependencySynchronize();

    const float4 nz = *nzp;   // L2-broadcast LDG.128; loop-invariant

    #pragma unroll
    for (int k = 0; k < ADD_IT; ++k) {
        float4 t = e[k];
        t.x += nz.x; t.y += nz.y; t.z += nz.z; t.w += nz.w;
        __stcs(&out4[v0 + k * ADD_STRIDE], t);
    }
}

// ---------------------------------------------------------------------------
// Kernel B (general fallback): any shape. PDL-aware.
// ---------------------------------------------------------------------------
__global__ void __launch_bounds__(256) add_general_kernel(
        const float* __restrict__ embs, float* __restrict__ out,
        int n4, int n) {
    cudaGridDependencySynchronize();

    const float4* __restrict__ in4  = reinterpret_cast<const float4*>(embs);
    float4* __restrict__       out4 = reinterpret_cast<float4*>(out);

    const int stride = gridDim.x * blockDim.x;       // multiple of 75
    const int v0     = blockIdx.x * blockDim.x + threadIdx.x;
    const float4 nz  = reinterpret_cast<const float4*>(g_noise)[v0 % 75];

    for (int v = v0; v < n4; v += 8 * stride) {
        #pragma unroll
        for (int k = 0; k < 8; ++k) {
            const int vi = v + k * stride;
            if (vi < n4) {
                float4 t = __ldcs(&in4[vi]);
                t.x += nz.x; t.y += nz.y; t.z += nz.z; t.w += nz.w;
                __stcs(&out4[vi], t);
            }
        }
    }
    const int tail_start = n4 * 4;
    for (int i = tail_start + v0; i < n; i += stride)
        out[i] = embs[i] + g_noise[i % EMBS_DIM];
}

// ---------------------------------------------------------------------------
extern "C" void kernel_launch(void* const* d_in, const int* in_sizes, int n_in,
                              void* d_out, int out_size) {
    const float* embs = (const float*)d_in[0];
    const float* sgn  = (const float*)d_in[1];
    const float* u    = (const float*)d_in[2];
    float* out        = (float*)d_out;

    const int nsamp = in_sizes[1];
    noise_kernel<<<1, T_N>>>(sgn, u, nsamp);

    const int n  = out_size;
    const int n4 = n / 4;

    if (n == n4 * 4 && n4 == ADD_GRID * ADD_BLK * ADD_IT) {
        cudaLaunchConfig_t cfg = {};
        cfg.gridDim  = dim3(ADD_GRID, 1, 1);
        cfg.blockDim = dim3(ADD_BLK, 1, 1);
        cudaLaunchAttribute attr[1];
        attr[0].id = cudaLaunchAttributeProgrammaticStreamSerialization;
        attr[0].val.programmaticStreamSerializationAllowed = 1;
        cfg.attrs = attr;
        cfg.numAttrs = 1;
        cudaError_t e = cudaLaunchKernelEx(&cfg, add_exact_kernel, embs, out);
        if (e != cudaSuccess) {
            (void)cudaGetLastError();               // clear sticky error
            add_exact_kernel<<<ADD_GRID, ADD_BLK>>>(embs, out);
        }
    } else {
        int grid = (n4 + 256 * 8 - 1) / (256 * 8);
        grid = ((grid + 74) / 75) * 75;             // stride % 75 == 0
        if (grid < 75) grid = 75;
        add_general_kernel<<<grid, 256>>>(embs, out, n4, n);
    }
}